// round 14
// baseline (speedup 1.0000x reference)
#include <cuda_runtime.h>
#include <cuda_fp16.h>
#include <cstdint>

#define B_BATCH   128
#define T_STEPS   500
#define K_DIM     700
#define KP        704
#define N_DIM     1024
#define M_DIM     64000

#define PHI_C    0.36787944117144233f
#define GAMMA_C  0.8187307530779818f
#define BETA_C   0.9048374180359595f
#define U_TH_C   1.0f
#define EPS_FLAG 3.0e-4f

#define NCOL_F   80          // fp32 columns per 128-tile
#define NCOL_T   48          // tensor columns per 128-tile

__device__ float g_inputs[(size_t)M_DIM * N_DIM];
__device__ __half g_asplit[2ull * M_DIM * KP];     // hi, lo (natural scale)
__device__ __half g_bsplit[2ull * N_DIM * KP];     // hi*2048, lo*2048
__device__ unsigned char g_flags[B_BATCH * N_DIM];

#define A_PLANE ((size_t)M_DIM * KP)
#define B_PLANE ((size_t)N_DIM * KP)

// ---------------------------------------------------------------------------
// Split: fp32 -> 2x fp16 planes (hi, lo), optional power-of-2 scale (exact)
// ---------------------------------------------------------------------------
__global__ __launch_bounds__(256) void split16_kernel(
    const float* __restrict__ src, __half* __restrict__ dst,
    int rows, size_t plane, float scale)
{
    int idx = blockIdx.x * blockDim.x + threadIdx.x;
    int r = idx / (KP / 8);
    int u = idx % (KP / 8);
    if (r >= rows) return;
    int k = u * 8;
    __half h0[8], h1[8];
#pragma unroll
    for (int i = 0; i < 8; i++) {
        float x = (k + i < K_DIM) ? src[(size_t)r * K_DIM + k + i] : 0.0f;
        __half hi = __float2half(x);                 // round at natural scale
        float lo = x - __half2float(hi);
        h0[i] = __float2half(__half2float(hi) * scale);  // exact exponent shift
        h1[i] = __float2half(lo * scale);
    }
    size_t off = (size_t)r * KP + k;
    *(uint4*)(dst + off)         = *(uint4*)h0;
    *(uint4*)(dst + plane + off) = *(uint4*)h1;
}

// ---------------------------------------------------------------------------
// Hybrid GEMM, 512 threads. CTA = 128x128 tile, C[m,n] = sum_k A[m,k]W[n,k].
//  warps 0-7  (2/SMSP): cols [0,80)    bit-exact fp32 FFMA
//  warps 8-15 (2/SMSP): cols [80,128)  fp16 2-split 3-pass mma.sync
// ---------------------------------------------------------------------------
#define T_APL     10240                    // A plane: 128 rows x 80 B
#define T_BPL     3840                     // B plane: 48 rows x 80 B
#define T_STAGE   (2 * T_APL + 2 * T_BPL)  // 28160
#define T_NST     4
#define T_NCH     22                       // 704/32
#define FP_OFF    (T_NST * T_STAGE)        // 112640 B
#define AS_STRIDE 132
#define BS_STRIDE 84
#define AS_OFF_F  (FP_OFF / 4)             // 28160 floats
#define BS_OFF_F  (AS_OFF_F + 16 * AS_STRIDE)
#define DYN_SMEM  (FP_OFF + (16 * AS_STRIDE + 16 * BS_STRIDE) * 4)  // 126464
#define F_NCH     44                       // ceil(700/16)

__device__ __forceinline__ uint32_t smem_u32(const void* p) {
    uint32_t a;
    asm("{ .reg .u64 t; cvta.to.shared.u64 t, %1; cvt.u32.u64 %0, t; }" : "=r"(a) : "l"(p));
    return a;
}
__device__ __forceinline__ void ldsm_x4(uint32_t addr, uint32_t& r0, uint32_t& r1,
                                        uint32_t& r2, uint32_t& r3) {
    asm volatile("ldmatrix.sync.aligned.m8n8.x4.shared.b16 {%0,%1,%2,%3}, [%4];"
                 : "=r"(r0), "=r"(r1), "=r"(r2), "=r"(r3) : "r"(addr));
}
__device__ __forceinline__ void mma16816h(float* d, const uint32_t* a, const uint32_t* b) {
    asm volatile(
        "mma.sync.aligned.m16n8k16.row.col.f32.f16.f16.f32 "
        "{%0,%1,%2,%3}, {%4,%5,%6,%7}, {%8,%9}, {%0,%1,%2,%3};"
        : "+f"(d[0]), "+f"(d[1]), "+f"(d[2]), "+f"(d[3])
        : "r"(a[0]), "r"(a[1]), "r"(a[2]), "r"(a[3]), "r"(b[0]), "r"(b[1]));
}
__device__ __forceinline__ void bar_named(int id, int cnt) {
    asm volatile("bar.sync %0, %1;" :: "r"(id), "r"(cnt) : "memory");
}

// tensor stage loader: 256 threads; one 32-k chunk; 1408 x 16B
__device__ __forceinline__ void t_load_stage(
    int chunk, int s, int ltid, int m0, int n0, uint32_t smem_base,
    const __half* __restrict__ Asp, const __half* __restrict__ Bsp)
{
    const int k0 = chunk * 32;
    const uint32_t sb = smem_base + s * T_STAGE;
#pragma unroll
    for (int it = 0; it < 6; ++it) {
        int idx = ltid + it * 256;            // need 0..1407
        if (idx >= 1408) break;
        const __half* src;
        uint32_t dst;
        if (idx < 1024) {                     // A: 2 planes x 512
            int pl = idx >> 9, rem = idx & 511, r = rem >> 2, u = rem & 3;
            src = Asp + (size_t)pl * A_PLANE + (size_t)(m0 + r) * KP + k0 + u * 8;
            dst = sb + pl * T_APL + r * 80 + u * 16;
        } else {                              // B: 2 planes x 192
            int ib = idx - 1024;
            int pl = ib / 192, rem = ib % 192, r = rem >> 2, u = rem & 3;
            src = Bsp + (size_t)pl * B_PLANE + (size_t)(n0 + NCOL_F + r) * KP + k0 + u * 8;
            dst = sb + 2 * T_APL + pl * T_BPL + r * 80 + u * 16;
        }
        asm volatile("cp.async.cg.shared.global [%0], [%1], 16;" :: "r"(dst), "l"(src));
    }
    asm volatile("cp.async.commit_group;" ::: "memory");
}

__global__ __launch_bounds__(512, 1) void gemm_hybrid_kernel(
    const float* __restrict__ X,
    const float* __restrict__ W,
    const __half* __restrict__ Asp,
    const __half* __restrict__ Bsp,
    float* __restrict__ C)
{
    extern __shared__ __align__(128) char smem[];
    const uint32_t smem_base = smem_u32(smem);
    float* smf = (float*)smem;
    const int tid  = threadIdx.x;
    const int lane = tid & 31;
    const int wid  = tid >> 5;
    const int m0   = blockIdx.y * 128;
    const int n0   = blockIdx.x * 128;

    if (wid < 8) {
        // ============ fp32 group: 256 threads, cols [0,80) =================
        const int ltid = tid;
        const int trow = ltid >> 4;           // 0..15
        const int tcol = ltid & 15;           // 0..15
        const int mloc = trow * 8;
        // thread covers cols {tcol + 16j, j<5}

        float acc[8][5];
#pragma unroll
        for (int i = 0; i < 8; i++)
#pragma unroll
            for (int j = 0; j < 5; j++) acc[i][j] = 0.f;

        float4 av[2], bv[2];
        // prefetch chunk 0
        {
#pragma unroll
            for (int l = 0; l < 2; ++l) {
                int f = ltid + l * 256, row = f >> 2, u = f & 3, kg = u * 4;
                av[l] = (kg < K_DIM) ? *(const float4*)(X + (size_t)(m0 + row) * K_DIM + kg)
                                     : make_float4(0, 0, 0, 0);
            }
            bv[0] = make_float4(0, 0, 0, 0);
            bv[1] = make_float4(0, 0, 0, 0);
            {
                int row = ltid >> 2, u = ltid & 3, kg = u * 4;
                if (kg < K_DIM)
                    bv[0] = *(const float4*)(W + (size_t)(n0 + row) * K_DIM + kg);
            }
            if (ltid < 64) {
                int f = ltid + 256, row = f >> 2, u = f & 3, kg = u * 4;
                if (kg < K_DIM)
                    bv[1] = *(const float4*)(W + (size_t)(n0 + row) * K_DIM + kg);
            }
        }

        for (int c = 0; c < F_NCH; ++c) {
            // store prefetched regs -> smem transposed
#pragma unroll
            for (int l = 0; l < 2; ++l) {
                int f = ltid + l * 256, row = f >> 2, u = f & 3;
                smf[AS_OFF_F + (u * 4 + 0) * AS_STRIDE + row] = av[l].x;
                smf[AS_OFF_F + (u * 4 + 1) * AS_STRIDE + row] = av[l].y;
                smf[AS_OFF_F + (u * 4 + 2) * AS_STRIDE + row] = av[l].z;
                smf[AS_OFF_F + (u * 4 + 3) * AS_STRIDE + row] = av[l].w;
            }
            {
                int row = ltid >> 2, u = ltid & 3;
                smf[BS_OFF_F + (u * 4 + 0) * BS_STRIDE + row] = bv[0].x;
                smf[BS_OFF_F + (u * 4 + 1) * BS_STRIDE + row] = bv[0].y;
                smf[BS_OFF_F + (u * 4 + 2) * BS_STRIDE + row] = bv[0].z;
                smf[BS_OFF_F + (u * 4 + 3) * BS_STRIDE + row] = bv[0].w;
            }
            if (ltid < 64) {
                int f = ltid + 256, row = f >> 2, u = f & 3;
                smf[BS_OFF_F + (u * 4 + 0) * BS_STRIDE + row] = bv[1].x;
                smf[BS_OFF_F + (u * 4 + 1) * BS_STRIDE + row] = bv[1].y;
                smf[BS_OFF_F + (u * 4 + 2) * BS_STRIDE + row] = bv[1].z;
                smf[BS_OFF_F + (u * 4 + 3) * BS_STRIDE + row] = bv[1].w;
            }
            bar_named(1, 256);

            // prefetch next chunk
            if (c + 1 < F_NCH) {
                const int k0 = (c + 1) * 16;
#pragma unroll
                for (int l = 0; l < 2; ++l) {
                    int f = ltid + l * 256, row = f >> 2, u = f & 3, kg = k0 + u * 4;
                    av[l] = (kg < K_DIM) ? *(const float4*)(X + (size_t)(m0 + row) * K_DIM + kg)
                                         : make_float4(0, 0, 0, 0);
                }
                {
                    int row = ltid >> 2, u = ltid & 3, kg = k0 + u * 4;
                    bv[0] = (kg < K_DIM) ? *(const float4*)(W + (size_t)(n0 + row) * K_DIM + kg)
                                         : make_float4(0, 0, 0, 0);
                }
                if (ltid < 64) {
                    int f = ltid + 256, row = f >> 2, u = f & 3, kg = k0 + u * 4;
                    bv[1] = (kg < K_DIM) ? *(const float4*)(W + (size_t)(n0 + row) * K_DIM + kg)
                                         : make_float4(0, 0, 0, 0);
                }
            }

            // 16 ascending k-steps (bit-exact chain per (m,n))
#pragma unroll
            for (int k = 0; k < 16; ++k) {
                float4 a0 = *(float4*)&smf[AS_OFF_F + k * AS_STRIDE + mloc];
                float4 a1 = *(float4*)&smf[AS_OFF_F + k * AS_STRIDE + mloc + 4];
                float a[8] = {a0.x, a0.y, a0.z, a0.w, a1.x, a1.y, a1.z, a1.w};
                float b[5];
#pragma unroll
                for (int j = 0; j < 5; ++j)
                    b[j] = smf[BS_OFF_F + k * BS_STRIDE + tcol + 16 * j];
#pragma unroll
                for (int i = 0; i < 8; ++i)
#pragma unroll
                    for (int j = 0; j < 5; ++j)
                        acc[i][j] = fmaf(a[i], b[j], acc[i][j]);
            }
            bar_named(1, 256);
        }

        // epilogue: lanes with same trow write consecutive cols -> coalesced
#pragma unroll
        for (int i = 0; i < 8; ++i) {
            float* cp = C + (size_t)(m0 + mloc + i) * N_DIM + n0 + tcol;
#pragma unroll
            for (int j = 0; j < 5; ++j)
                cp[16 * j] = acc[i][j];
        }
    } else {
        // ============ tensor group: 256 threads, cols [80,128) =============
        const int ltid = tid - 256;           // 0..255
        const int tw   = wid - 8;             // 0..7 -> rows tw*16..+16

        float acc[6][4];
#pragma unroll
        for (int t = 0; t < 6; t++)
#pragma unroll
            for (int f = 0; f < 4; f++) acc[t][f] = 0.f;

        t_load_stage(0, 0, ltid, m0, n0, smem_base, Asp, Bsp);
        t_load_stage(1, 1, ltid, m0, n0, smem_base, Asp, Bsp);
        t_load_stage(2, 2, ltid, m0, n0, smem_base, Asp, Bsp);

        const uint32_t a_row = lane & 15;
        const uint32_t a_kb  = ((lane >> 4) & 1) * 16;
        const uint32_t b_row = ((lane >> 4) & 1) * 8 + (lane & 7);
        const uint32_t b_kb  = ((lane >> 3) & 1) * 16;

        for (int c = 0; c < T_NCH; ++c) {
            const int s = c & 3;
            if (c == T_NCH - 1)
                asm volatile("cp.async.wait_group 0;" ::: "memory");
            else
                asm volatile("cp.async.wait_group 2;" ::: "memory");
            bar_named(2, 256);

            if (c + 3 < T_NCH)
                t_load_stage(c + 3, (c + 3) & 3, ltid, m0, n0, smem_base, Asp, Bsp);
            else
                asm volatile("cp.async.commit_group;" ::: "memory");  // keep depth uniform

            const uint32_t sA = smem_base + s * T_STAGE;
            const uint32_t sB = sA + 2 * T_APL;
#pragma unroll
            for (int ks = 0; ks < 2; ++ks) {
                uint32_t bh[6][2], bl[6][2];
#pragma unroll
                for (int j = 0; j < 3; ++j) {
                    uint32_t ar = sB + (j * 16 + b_row) * 80 + ks * 32 + b_kb;
                    ldsm_x4(ar, bh[2 * j][0], bh[2 * j][1], bh[2 * j + 1][0], bh[2 * j + 1][1]);
                    ldsm_x4(ar + T_BPL, bl[2 * j][0], bl[2 * j][1],
                            bl[2 * j + 1][0], bl[2 * j + 1][1]);
                }
                uint32_t ah[4], al[4];
                {
                    uint32_t ar = sA + (tw * 16 + a_row) * 80 + ks * 32 + a_kb;
                    ldsm_x4(ar, ah[0], ah[1], ah[2], ah[3]);
                    ldsm_x4(ar + T_APL, al[0], al[1], al[2], al[3]);
                }
#pragma unroll
                for (int t = 0; t < 6; ++t) mma16816h(acc[t], ah, bh[t]);  // hh
#pragma unroll
                for (int t = 0; t < 6; ++t) mma16816h(acc[t], ah, bl[t]);  // hi*lo
#pragma unroll
                for (int t = 0; t < 6; ++t) mma16816h(acc[t], al, bh[t]);  // lo*hi
            }
        }

        // epilogue: scale back by 2^-11 (exact)
        const int erow = lane >> 2;
        const int ecol = (lane & 3) * 2;
        const float sc = 1.0f / 2048.0f;
#pragma unroll
        for (int t = 0; t < 6; ++t) {
            float* cp = C + (size_t)(m0 + tw * 16 + erow) * N_DIM + n0 + NCOL_F + t * 8 + ecol;
            *(float2*)cp = make_float2(acc[t][0] * sc, acc[t][1] * sc);
            *(float2*)(cp + 8 * N_DIM) = make_float2(acc[t][2] * sc, acc[t][3] * sc);
        }
    }
}

// ---------------------------------------------------------------------------
// LIF scan + flag (R1 config: 512 blocks x 256, one channel per thread)
// ---------------------------------------------------------------------------
__global__ __launch_bounds__(256) void lif_scan_flag_kernel(
    const float* __restrict__ inp, float* __restrict__ Uo,
    float* __restrict__ So, unsigned char* __restrict__ flags)
{
    int idx = blockIdx.x * blockDim.x + threadIdx.x;
    int b = idx >> 10;
    int h = idx & (N_DIM - 1);
    size_t base = (size_t)b * T_STEPS * N_DIM + h;
    const float* ip = inp + base;
    float* up = Uo + base;
    float* sp = So + base;

    up[0] = 0.0f;
    sp[0] = 0.0f;
    float H = 0.f, I = 0.f, U = 0.f, S = 0.f;
    int flagged = 0;
#pragma unroll 4
    for (int t = 1; t < T_STEPS; t++) {
        float x  = ip[(size_t)(t - 1) * N_DIM];
        float Hn = PHI_C * H + x;
        float In = GAMMA_C * I + H;
        float Un = BETA_C * (U - I) - S;
        float Sn = (Un > U_TH_C) ? 1.0f : 0.0f;
        flagged |= (fabsf(Un - U_TH_C) < EPS_FLAG) ? 1 : 0;
        up[(size_t)t * N_DIM] = Un;
        sp[(size_t)t * N_DIM] = Sn;
        H = Hn; I = In; U = Un; S = Sn;
    }
    flags[idx] = (unsigned char)(flagged && ((h & 127) >= NCOL_F));
}

// ---------------------------------------------------------------------------
// Repair: bit-exact recompute of flagged channels (one block per batch)
// ---------------------------------------------------------------------------
#define NH_BATCH 8
#define RPR_SX    0
#define RPR_SW    16500
#define RPR_SINP  (16500 + 5632)
#define RPR_SMEM  ((16500 + 5632 + 4000) * 4)

__global__ __launch_bounds__(512) void lif_repair_kernel(
    const float* __restrict__ X, const float* __restrict__ W,
    const unsigned char* __restrict__ flags,
    float* __restrict__ Uo, float* __restrict__ So)
{
    extern __shared__ float rsm[];
    float* sX   = rsm + RPR_SX;
    float* sW   = rsm + RPR_SW;
    float* sInp = rsm + RPR_SINP;
    __shared__ int hlist[N_DIM];
    __shared__ int hcount;

    const int b = blockIdx.x;
    const int tid = threadIdx.x;

    if (tid == 0) {
        int cnt = 0;
        for (int h = 0; h < N_DIM; ++h)
            if (flags[b * N_DIM + h]) hlist[cnt++] = h;
        hcount = cnt;
    }
    __syncthreads();
    const int nflag = hcount;

    for (int bi = 0; bi < nflag; bi += NH_BATCH) {
        const int nh = min(NH_BATCH, nflag - bi);
        for (int i = tid; i < nh * 704; i += 512) {
            int j = i / 704, k = i - j * 704;
            sW[j * 704 + k] = (k < K_DIM) ? W[(size_t)hlist[bi + j] * K_DIM + k] : 0.f;
        }
        __syncthreads();

        float c8[NH_BATCH];
#pragma unroll
        for (int j = 0; j < NH_BATCH; ++j) c8[j] = 0.f;

        for (int kc = 0; kc < K_DIM; kc += 32) {
            const int kw = (K_DIM - kc < 32) ? (K_DIM - kc) : 32;
            for (int i = tid; i < T_STEPS * kw; i += 512) {
                int tt = i / kw, kk = i - tt * kw;
                sX[tt * 33 + kk] = X[((size_t)b * T_STEPS + tt) * K_DIM + kc + kk];
            }
            __syncthreads();
            if (tid < T_STEPS) {
#pragma unroll
                for (int j = 0; j < NH_BATCH; ++j) {
                    float c = c8[j];
                    for (int kk = 0; kk < kw; ++kk)
                        c = fmaf(sX[tid * 33 + kk], sW[j * 704 + kc + kk], c);
                    c8[j] = c;
                }
            }
            __syncthreads();
        }
        if (tid < T_STEPS)
#pragma unroll
            for (int j = 0; j < NH_BATCH; ++j)
                if (j < nh) sInp[j * T_STEPS + tid] = c8[j];
        __syncthreads();

        if (tid < nh) {
            const int h = hlist[bi + tid];
            size_t base = (size_t)b * T_STEPS * N_DIM + h;
            Uo[base] = 0.0f;
            So[base] = 0.0f;
            float H = 0.f, I = 0.f, U = 0.f, S = 0.f;
            for (int t = 1; t < T_STEPS; t++) {
                float x  = sInp[tid * T_STEPS + (t - 1)];
                float Hn = PHI_C * H + x;
                float In = GAMMA_C * I + H;
                float Un = BETA_C * (U - I) - S;
                float Sn = (Un > U_TH_C) ? 1.0f : 0.0f;
                Uo[base + (size_t)t * N_DIM] = Un;
                So[base + (size_t)t * N_DIM] = Sn;
                H = Hn; I = In; U = Un; S = Sn;
            }
        }
        __syncthreads();
    }
}

// ---------------------------------------------------------------------------
extern "C" void kernel_launch(void* const* d_in, const int* in_sizes, int n_in,
                              void* d_out, int out_size)
{
    const float* X = (const float*)d_in[0];
    const float* W = (const float*)d_in[1];
    float* out = (float*)d_out;

    float* inputs;         cudaGetSymbolAddress((void**)&inputs, g_inputs);
    __half* asplit;        cudaGetSymbolAddress((void**)&asplit, g_asplit);
    __half* bsplit;        cudaGetSymbolAddress((void**)&bsplit, g_bsplit);
    unsigned char* flags;  cudaGetSymbolAddress((void**)&flags, g_flags);

    cudaFuncSetAttribute(gemm_hybrid_kernel,
                         cudaFuncAttributeMaxDynamicSharedMemorySize, DYN_SMEM);
    cudaFuncSetAttribute(lif_repair_kernel,
                         cudaFuncAttributeMaxDynamicSharedMemorySize, RPR_SMEM);

    // 1. fp16 2-plane splits (A natural, B pre-scaled by 2048)
    split16_kernel<<<(M_DIM * (KP / 8) + 255) / 256, 256>>>(X, asplit, M_DIM, A_PLANE, 1.0f);
    split16_kernel<<<(N_DIM * (KP / 8) + 255) / 256, 256>>>(W, bsplit, N_DIM, B_PLANE, 2048.0f);

    // 2. hybrid GEMM
    dim3 ggrid(N_DIM / 128, M_DIM / 128);     // (8, 500)
    gemm_hybrid_kernel<<<ggrid, 512, DYN_SMEM>>>(X, W, asplit, bsplit, inputs);

    // 3. LIF scan + flags
    float* Uo = out;
    float* So = out + (size_t)B_BATCH * T_STEPS * N_DIM;
    lif_scan_flag_kernel<<<(B_BATCH * N_DIM) / 256, 256>>>(inputs, Uo, So, flags);

    // 4. bit-exact repair of flagged tensor-column channels
    lif_repair_kernel<<<B_BATCH, 512, RPR_SMEM>>>(X, W, flags, Uo, So);
}

// round 15
// speedup vs baseline: 2.0288x; 2.0288x over previous
#include <cuda_runtime.h>
#include <cstdint>

// Problem dims
#define B_BATCH   128
#define T_STEPS   500
#define K_DIM     700      // in_features
#define N_DIM     1024     // out_features (hidden)
#define M_DIM     (B_BATCH * T_STEPS)   // 64000

// LIF constants
#define PHI_C    0.36787944117144233f   // exp(-1)
#define GAMMA_C  0.8187307530779818f    // exp(-0.2)
#define BETA_C   0.9048374180359595f    // exp(-0.1)
#define U_TH_C   1.0f

// Scratch: inputs[b,t,h] = X @ W^T   (64000 x 1024 fp32 = 262 MB)
__device__ float g_inputs[(size_t)M_DIM * N_DIM];

// ---------------------------------------------------------------------------
// GEMM:  C[m,n] = sum_k A[m,k] * B[n,k]    (NT, fp32, exact FMA, ascending k)
// Tiles: BM=128, BN=128, BK=16, 256 threads, 8x8 micro-tile per thread.
// Register double-buffering: chunk c+1's global loads issue during chunk c's
// compute, hiding LDG latency. Accumulation order identical to R1 (bit-exact).
// ---------------------------------------------------------------------------
#define BM 128
#define BN 128
#define BK 16
#define SPAD 4
#define NCH 44   // ceil(700/16)

__global__ __launch_bounds__(256) void gemm_nt_kernel(
    const float* __restrict__ A,   // [M_DIM, K_DIM]
    const float* __restrict__ Bw,  // [N_DIM, K_DIM]
    float* __restrict__ C)         // [M_DIM, N_DIM]
{
    __shared__ float As[BK][BM + SPAD];
    __shared__ float Bs[BK][BN + SPAD];

    const int tid = threadIdx.x;
    const int tx  = tid & 15;        // n micro-tile
    const int ty  = tid >> 4;        // m micro-tile
    const int m0  = blockIdx.y * BM;
    const int n0  = blockIdx.x * BN;

    // 8 rows x 4 packed col-pairs of f32x2 accumulators (R1-identical)
    unsigned long long acc[8][4];
#pragma unroll
    for (int i = 0; i < 8; i++)
#pragma unroll
        for (int j = 0; j < 4; j++) acc[i][j] = 0ULL;

    float4 pa[2], pb[2];

    // --- prefetch chunk 0 into registers ---
    {
        const int kk = 0;
#pragma unroll
        for (int l = 0; l < 2; l++) {
            int f = tid + l * 256, row = f >> 2, kq = f & 3, kg = kk + kq * 4;
            pa[l] = (kg < K_DIM)
                ? *(const float4*)(A + (size_t)(m0 + row) * K_DIM + kg)
                : make_float4(0.f, 0.f, 0.f, 0.f);
        }
#pragma unroll
        for (int l = 0; l < 2; l++) {
            int f = tid + l * 256, row = f >> 2, kq = f & 3, kg = kk + kq * 4;
            pb[l] = (kg < K_DIM)
                ? *(const float4*)(Bw + (size_t)(n0 + row) * K_DIM + kg)
                : make_float4(0.f, 0.f, 0.f, 0.f);
        }
    }

    for (int c = 0; c < NCH; ++c) {
        // ---- store prefetched registers -> smem (k-transposed) ----
#pragma unroll
        for (int l = 0; l < 2; l++) {
            int f = tid + l * 256, row = f >> 2, kq = f & 3;
            As[kq * 4 + 0][row] = pa[l].x;
            As[kq * 4 + 1][row] = pa[l].y;
            As[kq * 4 + 2][row] = pa[l].z;
            As[kq * 4 + 3][row] = pa[l].w;
        }
#pragma unroll
        for (int l = 0; l < 2; l++) {
            int f = tid + l * 256, row = f >> 2, kq = f & 3;
            Bs[kq * 4 + 0][row] = pb[l].x;
            Bs[kq * 4 + 1][row] = pb[l].y;
            Bs[kq * 4 + 2][row] = pb[l].z;
            Bs[kq * 4 + 3][row] = pb[l].w;
        }
        __syncthreads();

        // ---- issue next chunk's global loads (latency hidden by compute) ----
        if (c + 1 < NCH) {
            const int kk = (c + 1) * BK;
#pragma unroll
            for (int l = 0; l < 2; l++) {
                int f = tid + l * 256, row = f >> 2, kq = f & 3, kg = kk + kq * 4;
                pa[l] = (kg < K_DIM)
                    ? *(const float4*)(A + (size_t)(m0 + row) * K_DIM + kg)
                    : make_float4(0.f, 0.f, 0.f, 0.f);
            }
#pragma unroll
            for (int l = 0; l < 2; l++) {
                int f = tid + l * 256, row = f >> 2, kq = f & 3, kg = kk + kq * 4;
                pb[l] = (kg < K_DIM)
                    ? *(const float4*)(Bw + (size_t)(n0 + row) * K_DIM + kg)
                    : make_float4(0.f, 0.f, 0.f, 0.f);
            }
        }

        // ---- compute 16 k-steps (R1-identical inner loop, ascending k) ----
#pragma unroll
        for (int k = 0; k < BK; k++) {
            float4 av0 = *(const float4*)&As[k][ty * 8 + 0];
            float4 av1 = *(const float4*)&As[k][ty * 8 + 4];
            float a[8] = {av0.x, av0.y, av0.z, av0.w, av1.x, av1.y, av1.z, av1.w};
            unsigned long long b2[4];
            const unsigned long long* bp = (const unsigned long long*)&Bs[k][tx * 8];
            b2[0] = bp[0]; b2[1] = bp[1]; b2[2] = bp[2]; b2[3] = bp[3];
#pragma unroll
            for (int i = 0; i < 8; i++) {
                unsigned long long a2;
                asm("mov.b64 %0, {%1, %1};" : "=l"(a2) : "f"(a[i]));
#pragma unroll
                for (int j = 0; j < 4; j++)
                    asm("fma.rn.f32x2 %0, %1, %2, %0;"
                        : "+l"(acc[i][j]) : "l"(a2), "l"(b2[j]));
            }
        }
        __syncthreads();
    }

    // ---- epilogue: 2x STG.128 per row (R1-identical) ----
#pragma unroll
    for (int i = 0; i < 8; i++) {
        float* cp = C + (size_t)(m0 + ty * 8 + i) * N_DIM + n0 + tx * 8;
        *(float4*)(cp + 0) = *(float4*)&acc[i][0];
        *(float4*)(cp + 4) = *(float4*)&acc[i][2];
    }
}

// ---------------------------------------------------------------------------
// LIF scan: one thread per (b, h); sequential over t; coalesced in h.
// (R1-identical — proven 153 us)
// ---------------------------------------------------------------------------
__global__ __launch_bounds__(256) void lif_scan_kernel(
    const float* __restrict__ inp,  // [B*T, N] == [b, t, h]
    float* __restrict__ Uo,         // [B, T, N]
    float* __restrict__ So)         // [B, T, N]
{
    int idx = blockIdx.x * blockDim.x + threadIdx.x;  // 0 .. B*N-1
    int b = idx >> 10;
    int h = idx & (N_DIM - 1);
    size_t base = (size_t)b * T_STEPS * N_DIM + h;

    const float* ip = inp + base;
    float* up = Uo + base;
    float* sp = So + base;

    up[0] = 0.0f;
    sp[0] = 0.0f;

    float H = 0.f, I = 0.f, U = 0.f, S = 0.f;
#pragma unroll 4
    for (int t = 1; t < T_STEPS; t++) {
        float x  = ip[(size_t)(t - 1) * N_DIM];
        float Hn = PHI_C * H + x;
        float In = GAMMA_C * I + H;
        float Un = BETA_C * (U - I) - S;
        float Sn = (Un > U_TH_C) ? 1.0f : 0.0f;
        up[(size_t)t * N_DIM] = Un;
        sp[(size_t)t * N_DIM] = Sn;
        H = Hn; I = In; U = Un; S = Sn;
    }
}

// ---------------------------------------------------------------------------
extern "C" void kernel_launch(void* const* d_in, const int* in_sizes, int n_in,
                              void* d_out, int out_size)
{
    const float* X = (const float*)d_in[0];  // [128, 500, 700]
    const float* W = (const float*)d_in[1];  // [1024, 700]
    float* out = (float*)d_out;              // U then S, each [128,500,1024]

    float* inputs;
    cudaGetSymbolAddress((void**)&inputs, g_inputs);

    dim3 ggrid(N_DIM / BN, M_DIM / BM);      // (8, 500)
    gemm_nt_kernel<<<ggrid, 256>>>(X, W, inputs);

    float* Uo = out;
    float* So = out + (size_t)B_BATCH * T_STEPS * N_DIM;
    int nthreads = B_BATCH * N_DIM;          // 131072
    lif_scan_kernel<<<nthreads / 256, 256>>>(inputs, Uo, So);
}